// round 1
// baseline (speedup 1.0000x reference)
#include <cuda_runtime.h>

// GraphConvolution: out = scatter_add(edge_val * (x@W)[edge_col] -> edge_row) + b
// N=50000, E=800000, D_IN=D_OUT=96
//
// Inputs (metadata order): x[N*96] f32, edge_row[E] i32, edge_col[E] i32,
//                          edge_val[E] f32, weight[96*96] f32, b[96] f32
// Output: out[N*96] f32

#define DIN  96
#define DOUT 96
#define MAXN 50000

// scratch for support = x @ W  (device global: no allocations allowed)
__device__ float g_support[(size_t)MAXN * DOUT];

// ---------------------------------------------------------------------------
// out[i][c] = b[c]
__global__ void init_out_kernel(float* __restrict__ out,
                                const float* __restrict__ b, int total) {
    int i = blockIdx.x * blockDim.x + threadIdx.x;
    if (i < total) {
        int c = i - (i / DOUT) * DOUT;
        out[i] = __ldg(b + c);
    }
}

// ---------------------------------------------------------------------------
// support = x @ W.  W staged in shared (96x96 f32 = 36.8KB).
// blockDim = (24, 16): thread = (col4, row-within-tile); 16 rows per block.
__global__ void gemm_kernel(const float* __restrict__ x,
                            const float* __restrict__ w,
                            float* __restrict__ sup, int N) {
    __shared__ float4 Ws[DIN][DOUT / 4];   // Ws[k][c4] = W[k][4c4..4c4+3]

    int tid = threadIdx.y * 24 + threadIdx.x;   // 0..383
    const float4* w4 = (const float4*)w;
    for (int i = tid; i < DIN * DOUT / 4; i += 24 * 16) {
        Ws[i / (DOUT / 4)][i % (DOUT / 4)] = w4[i];
    }
    __syncthreads();

    int row = blockIdx.x * 16 + threadIdx.y;
    if (row >= N) return;
    int c4 = threadIdx.x;

    const float* xr = x + (size_t)row * DIN;
    float4 acc = make_float4(0.f, 0.f, 0.f, 0.f);
#pragma unroll 8
    for (int k = 0; k < DIN; k++) {
        float  xv = __ldg(xr + k);         // broadcast within warp, L1 hit
        float4 wv = Ws[k][c4];
        acc.x += xv * wv.x;
        acc.y += xv * wv.y;
        acc.z += xv * wv.z;
        acc.w += xv * wv.w;
    }
    ((float4*)(sup + (size_t)row * DOUT))[c4] = acc;
}

// ---------------------------------------------------------------------------
// Scatter: for each edge e, out[row[e]] += val[e] * support[col[e]]
// One thread per (edge, 4-col group): 24 threads per edge, float4 gather,
// 4 scalar fp32 atomicAdds (RED to L2-resident output).
__global__ void scatter_kernel(const int*   __restrict__ er,
                               const int*   __restrict__ ec,
                               const float* __restrict__ ev,
                               const float* __restrict__ sup,
                               float* __restrict__ out, int E) {
    int g = blockIdx.x * blockDim.x + threadIdx.x;
    int total = E * 24;                        // 19.2M < 2^31
    if (g >= total) return;
    int e  = g / 24;
    int c4 = g - e * 24;

    int   col = __ldg(ec + e);
    int   row = __ldg(er + e);
    float v   = __ldg(ev + e);

    float4 s = ((const float4*)(sup + (size_t)col * DOUT))[c4];
    float* o = out + (size_t)row * DOUT + c4 * 4;
    atomicAdd(o + 0, s.x * v);
    atomicAdd(o + 1, s.y * v);
    atomicAdd(o + 2, s.z * v);
    atomicAdd(o + 3, s.w * v);
}

// ---------------------------------------------------------------------------
extern "C" void kernel_launch(void* const* d_in, const int* in_sizes, int n_in,
                              void* d_out, int out_size) {
    const float* x      = (const float*)d_in[0];
    const int*   e_row  = (const int*)  d_in[1];
    const int*   e_col  = (const int*)  d_in[2];
    const float* e_val  = (const float*)d_in[3];
    const float* weight = (const float*)d_in[4];
    const float* bias   = (const float*)d_in[5];
    float*       out    = (float*)d_out;

    int N = in_sizes[0] / DIN;
    int E = in_sizes[1];

    float* sup;
    cudaGetSymbolAddress((void**)&sup, g_support);

    // 1) out = b (broadcast)
    {
        int total = N * DOUT;
        init_out_kernel<<<(total + 255) / 256, 256>>>(out, bias, total);
    }

    // 2) support = x @ W
    {
        dim3 blk(24, 16);
        gemm_kernel<<<(N + 15) / 16, blk>>>(x, weight, sup, N);
    }

    // 3) scatter-add over edges
    {
        long long total = (long long)E * 24;
        int nblk = (int)((total + 255) / 256);
        scatter_kernel<<<nblk, 256>>>(e_row, e_col, e_val, sup, out, E);
    }
}

// round 2
// speedup vs baseline: 2.4524x; 2.4524x over previous
#include <cuda_runtime.h>

// GraphConvolution: out = scatter_add(edge_val * (x@W)[edge_col] -> edge_row) + b
// N=50000, E=800000, D_IN=D_OUT=96

#define DIN  96
#define DOUT 96
#define MAXN 50000

__device__ float g_support[(size_t)MAXN * DOUT];

// ---------------------------------------------------------------------------
// out = broadcast(b), vectorized: one float4 per thread.
__global__ void init_out_kernel(float4* __restrict__ out4,
                                const float4* __restrict__ b4, int total4) {
    int i = blockIdx.x * blockDim.x + threadIdx.x;
    if (i < total4) {
        int c4 = i - (i / (DOUT / 4)) * (DOUT / 4);
        out4[i] = __ldg(b4 + c4);
    }
}

// ---------------------------------------------------------------------------
// support = x @ W.   W staged in shared (96x96 f32 = 36.8KB).
// 384 threads; each thread computes 4 rows x 4 cols.
// Per float4-k-chunk: 4 LDG.128 (x, broadcast) + 4 LDS.128 (W) + 64 FFMA.
__global__ void __launch_bounds__(384)
gemm_kernel(const float* __restrict__ x,
            const float* __restrict__ w,
            float* __restrict__ sup, int N) {
    __shared__ float4 Ws[DIN][DOUT / 4];       // Ws[k][c4] = W[k][4c4..]

    int tid = threadIdx.x;
    const float4* w4 = (const float4*)w;
#pragma unroll
    for (int i = tid; i < DIN * DOUT / 4; i += 384)
        Ws[i / (DOUT / 4)][i % (DOUT / 4)] = w4[i];
    __syncthreads();

    int c4 = tid % 24;
    int r0 = blockIdx.x * 64 + (tid / 24) * 4;

    const float4* xr[4];
    bool valid[4];
#pragma unroll
    for (int j = 0; j < 4; j++) {
        int row  = r0 + j;
        valid[j] = (row < N);
        int rowc = valid[j] ? row : (N - 1);
        xr[j] = (const float4*)(x + (size_t)rowc * DIN);
    }

    float4 acc[4];
#pragma unroll
    for (int j = 0; j < 4; j++) acc[j] = make_float4(0.f, 0.f, 0.f, 0.f);

#pragma unroll 4
    for (int kk = 0; kk < DIN / 4; kk++) {
        float4 xv[4];
#pragma unroll
        for (int j = 0; j < 4; j++) xv[j] = __ldg(xr[j] + kk);

#pragma unroll
        for (int t = 0; t < 4; t++) {
            float4 wv = Ws[kk * 4 + t][c4];
#pragma unroll
            for (int j = 0; j < 4; j++) {
                float xs = (t == 0) ? xv[j].x : (t == 1) ? xv[j].y
                                              : (t == 2) ? xv[j].z : xv[j].w;
                acc[j].x += xs * wv.x;
                acc[j].y += xs * wv.y;
                acc[j].z += xs * wv.z;
                acc[j].w += xs * wv.w;
            }
        }
    }

#pragma unroll
    for (int j = 0; j < 4; j++)
        if (valid[j])
            ((float4*)(sup + (size_t)(r0 + j) * DOUT))[c4] = acc[j];
}

// ---------------------------------------------------------------------------
// Scatter: out[row[e]] += val[e] * support[col[e]], via vectorized
// red.global.add.v4.f32 (sm_90+). 24 threads per edge, one float4 each.
__global__ void scatter_kernel(const int*   __restrict__ er,
                               const int*   __restrict__ ec,
                               const float* __restrict__ ev,
                               const float* __restrict__ sup,
                               float* __restrict__ out, int E) {
    int g = blockIdx.x * blockDim.x + threadIdx.x;
    int total = E * 24;
    if (g >= total) return;
    int e  = g / 24;
    int c4 = g - e * 24;

    int   col = __ldg(ec + e);
    int   row = __ldg(er + e);
    float v   = __ldg(ev + e);

    float4 s = ((const float4*)(sup + (size_t)col * DOUT))[c4];
    float4 r = make_float4(s.x * v, s.y * v, s.z * v, s.w * v);
    float* o = out + (size_t)row * DOUT + c4 * 4;

    asm volatile("red.global.add.v4.f32 [%0], {%1, %2, %3, %4};"
                 :: "l"(o), "f"(r.x), "f"(r.y), "f"(r.z), "f"(r.w)
                 : "memory");
}

// ---------------------------------------------------------------------------
extern "C" void kernel_launch(void* const* d_in, const int* in_sizes, int n_in,
                              void* d_out, int out_size) {
    const float* x      = (const float*)d_in[0];
    const int*   e_row  = (const int*)  d_in[1];
    const int*   e_col  = (const int*)  d_in[2];
    const float* e_val  = (const float*)d_in[3];
    const float* weight = (const float*)d_in[4];
    const float* bias   = (const float*)d_in[5];
    float*       out    = (float*)d_out;

    int N = in_sizes[0] / DIN;
    int E = in_sizes[1];

    float* sup;
    cudaGetSymbolAddress((void**)&sup, g_support);

    // 1) out = b
    {
        int total4 = N * (DOUT / 4);
        init_out_kernel<<<(total4 + 255) / 256, 256>>>(
            (float4*)out, (const float4*)bias, total4);
    }

    // 2) support = x @ W
    {
        gemm_kernel<<<(N + 63) / 64, 384>>>(x, weight, sup, N);
    }

    // 3) scatter-add over edges
    {
        long long total = (long long)E * 24;
        int nblk = (int)((total + 255) / 256);
        scatter_kernel<<<nblk, 256>>>(e_row, e_col, e_val, sup, out, E);
    }
}